// round 15
// baseline (speedup 1.0000x reference)
#include <cuda_runtime.h>
#include <cuda_fp16.h>
#include <mma.h>
#include <cstdint>

using namespace nvcuda;

#define NN 100000
#define EE 1600000
#define NPART 98   // ceil(NN/1024)

// ---------------------------------------------------------------------------
// Static device scratch — fp16 activations, row strides padded to 128B mult.
// ---------------------------------------------------------------------------
__device__ __align__(256) float  g_dinv[NN];
__device__ __align__(256) __half g_xx [NN * 64];    // stride 64 (true 36)
__device__ __align__(256) __half g_p0 [NN * 64];
__device__ __align__(256) __half g_a1 [NN * 336];   // not gathered, unpadded
__device__ __align__(256) __half g_tt2[NN * 192];   // stride 192 (true 168)
__device__ __align__(256) __half g_p2 [NN * 192];
__device__ __align__(256) __half g_tt3[NN * 96];    // stride 96 (true 84)
__device__ __align__(256) __half g_p3 [NN * 96];
__device__ __align__(256) __half g_tt4[NN * 64];    // stride 64 (true 42)
__device__ __align__(256) __half g_a4s[NN * 64];
__device__ __align__(256) __half g_p5 [NN * 64];

// fp16 weight planes, zero-padded to [Kp][Np]
__device__ __align__(256) __half g_w1[64 * 384];
__device__ __align__(256) __half g_w2[352 * 192];
__device__ __align__(256) __half g_w3[192 * 96];
__device__ __align__(256) __half g_w4[96 * 96];

__device__ __align__(256) int g_cnt[NN];
__device__ __align__(256) int g_off[NN + 1];
__device__ __align__(256) int g_adj[EE];
__device__ __align__(256) int g_part[NPART];

// ---------------------------------------------------------------------------
// half vector load/store helpers
// ---------------------------------------------------------------------------
template <int V>
__device__ __forceinline__ void ldh(const __half* p, float* f) {
    if constexpr (V == 8) {
        uint4 u = *(const uint4*)p;
        const __half2* h = (const __half2*)&u;
#pragma unroll
        for (int k = 0; k < 4; k++) {
            float2 t = __half22float2(h[k]);
            f[2 * k] = t.x; f[2 * k + 1] = t.y;
        }
    } else if constexpr (V == 4) {
        uint2 u = *(const uint2*)p;
        const __half2* h = (const __half2*)&u;
#pragma unroll
        for (int k = 0; k < 2; k++) {
            float2 t = __half22float2(h[k]);
            f[2 * k] = t.x; f[2 * k + 1] = t.y;
        }
    } else {
        uint32_t u = *(const uint32_t*)p;
        float2 t = __half22float2(*(const __half2*)&u);
        f[0] = t.x; f[1] = t.y;
    }
}
template <int V>
__device__ __forceinline__ void sth(__half* p, const float* f) {
    if constexpr (V == 8) {
        uint4 u;
        __half2* h = (__half2*)&u;
#pragma unroll
        for (int k = 0; k < 4; k++)
            h[k] = __floats2half2_rn(f[2 * k], f[2 * k + 1]);
        *(uint4*)p = u;
    } else if constexpr (V == 4) {
        uint2 u;
        __half2* h = (__half2*)&u;
#pragma unroll
        for (int k = 0; k < 2; k++)
            h[k] = __floats2half2_rn(f[2 * k], f[2 * k + 1]);
        *(uint2*)p = u;
    } else {
        __half2 h = __floats2half2_rn(f[0], f[1]);
        *(uint32_t*)p = *(uint32_t*)&h;
    }
}

// ---------------------------------------------------------------------------
// Fused prep: zero cnt, off[NN]=EE, convert W1..W4 to fp16 padded planes.
// Launched with >= max(NN, WTOT) threads.
// ---------------------------------------------------------------------------
__device__ __forceinline__ void wcvt(const float* W, __half* o, int j,
                                     int K, int Nd, int Np) {
    int k = j / Np, n = j - k * Np;
    float v = (k < K && n < Nd) ? W[(size_t)k * Nd + n] : 0.0f;
    o[j] = __float2half_rn(v);
}
#define W1N (64 * 384)
#define W2N (352 * 192)
#define W3N (192 * 96)
#define W4N (96 * 96)
#define WTOT (W1N + W2N + W3N + W4N)
__global__ void k_prep(const float* __restrict__ W1, const float* __restrict__ W2,
                       const float* __restrict__ W3, const float* __restrict__ W4,
                       __half* __restrict__ w1, __half* __restrict__ w2,
                       __half* __restrict__ w3, __half* __restrict__ w4,
                       int* __restrict__ cnt, int* __restrict__ off) {
    int i = blockIdx.x * blockDim.x + threadIdx.x;
    if (i == 0) off[NN] = EE;
    if (i < NN) cnt[i] = 0;
    if (i < W1N) wcvt(W1, w1, i, 35, 336, 384);
    else if (i < W1N + W2N) wcvt(W2, w2, i - W1N, 336, 168, 192);
    else if (i < W1N + W2N + W3N) wcvt(W3, w3, i - W1N - W2N, 168, 84, 96);
    else if (i < WTOT) wcvt(W4, w4, i - W1N - W2N - W3N, 84, 42, 96);
}

// ---------------------------------------------------------------------------
// CSR build
// ---------------------------------------------------------------------------
__global__ void k_count(const int* __restrict__ dst, int* cnt) {
    int e = blockIdx.x * blockDim.x + threadIdx.x;
    if (e < EE) atomicAdd(&cnt[dst[e]], 1);
}
__global__ void k_scan1(const int* __restrict__ cnt, int* __restrict__ off,
                        int* __restrict__ part, float* __restrict__ dinv) {
    __shared__ int s[1024];
    int t = threadIdx.x;
    int i = blockIdx.x * 1024 + t;
    int v = (i < NN) ? cnt[i] : 0;
    if (i < NN) dinv[i] = rsqrtf((float)v + 1.0f);
    s[t] = v;
    __syncthreads();
    for (int d = 1; d < 1024; d <<= 1) {
        int u = (t >= d) ? s[t - d] : 0;
        __syncthreads();
        s[t] += u;
        __syncthreads();
    }
    if (i < NN) off[i] = s[t] - v;          // block-local exclusive
    if (t == 1023) part[blockIdx.x] = s[1023];
}
// scan3: finalize offsets + fused pad/scale x -> xx (stride 64, half2 writes)
__global__ void k_scan3(int* __restrict__ off, const int* __restrict__ part,
                        const float* __restrict__ x, const float* __restrict__ dinv,
                        __half* __restrict__ xx) {
    __shared__ int s[128];
    int t = threadIdx.x;
    if (t < 128) s[t] = (t < NPART) ? part[t] : 0;
    __syncthreads();
    for (int d = 1; d < 128; d <<= 1) {
        int u = 0;
        if (t < 128 && t >= d) u = s[t - d];
        __syncthreads();
        if (t < 128) s[t] += u;
        __syncthreads();
    }
    int base = (blockIdx.x > 0) ? s[blockIdx.x - 1] : 0;   // exclusive prefix
    int i = blockIdx.x * 1024 + t;
    if (i < NN) off[i] += base;
    // pad+scale: xx[n, 0..63] = fp16(dinv[n]*x[n,c]) for c<35, else 0
    for (long j2 = (long)blockIdx.x * 1024 + t; j2 < (long)NN * 32; j2 += (long)NPART * 1024) {
        int n = (int)(j2 >> 5);
        int c = (int)(j2 & 31) * 2;
        float sc = dinv[n];
        float v0 = (c < 35) ? x[(size_t)n * 35 + c] * sc : 0.0f;
        float v1 = (c + 1 < 35) ? x[(size_t)n * 35 + c + 1] * sc : 0.0f;
        __half2 h = __floats2half2_rn(v0, v1);
        *(uint32_t*)(xx + (size_t)n * 64 + c) = *(uint32_t*)&h;
    }
}
// fill reusing cnt via atomic decrement
__global__ void k_fill(const int* __restrict__ src, const int* __restrict__ dst,
                       const int* __restrict__ off, int* cnt, int* __restrict__ adj) {
    int e = blockIdx.x * blockDim.x + threadIdx.x;
    if (e >= EE) return;
    int d = dst[e];
    int p = off[d] + atomicAdd(&cnt[d], -1) - 1;
    adj[p] = src[e];
}

// ---------------------------------------------------------------------------
// CSR gather aggregation, padded strides (fp32 accumulate, 4-way unrolled)
// D = physical stride; DT = true width (for RBS bias masking).
// ---------------------------------------------------------------------------
template <int D, int V, bool RBS, int BLK, int DT>
__global__ void __launch_bounds__(BLK)
k_agg(const int* __restrict__ off, const int* __restrict__ adj,
      const float* __restrict__ dinv, const __half* __restrict__ tt,
      const float* __restrict__ bias, __half* __restrict__ p) {
    constexpr int G = D / V;
    constexpr int NPB = BLK / G;
    int g = threadIdx.x / G;
    int c = (threadIdx.x - g * G) * V;
    int node = blockIdx.x * NPB + g;
    if (g >= NPB || node >= NN) return;
    int ib = off[node], ie = off[node + 1];
    float acc[V], acc2[V];
    float t0[V], t1[V], t2[V], t3[V];
    ldh<V>(tt + (size_t)node * D + c, acc);
#pragma unroll
    for (int v = 0; v < V; v++) acc2[v] = 0.0f;
    int i = ib;
    for (; i + 4 <= ie; i += 4) {
        int s0 = adj[i], s1 = adj[i + 1], s2 = adj[i + 2], s3 = adj[i + 3];
        ldh<V>(tt + (size_t)s0 * D + c, t0);
        ldh<V>(tt + (size_t)s1 * D + c, t1);
        ldh<V>(tt + (size_t)s2 * D + c, t2);
        ldh<V>(tt + (size_t)s3 * D + c, t3);
#pragma unroll
        for (int v = 0; v < V; v++) {
            acc[v]  += t0[v] + t1[v];
            acc2[v] += t2[v] + t3[v];
        }
    }
    for (; i < ie; i++) {
        int s0 = adj[i];
        ldh<V>(tt + (size_t)s0 * D + c, t0);
#pragma unroll
        for (int v = 0; v < V; v++) acc[v] += t0[v];
    }
    float sc = dinv[node];
#pragma unroll
    for (int v = 0; v < V; v++) {
        float f = (acc[v] + acc2[v]) * sc;
        if (RBS) f = ((c + v) < DT) ? fmaxf(f + bias[c + v], 0.0f) * sc : 0.0f;
        acc[v] = f;
    }
    sth<V>(p + (size_t)node * D + c, acc);
}

// ---------------------------------------------------------------------------
// wmma fp16 GEMM, register-staged double-buffered chunks.
// Block 128x96, 8 warps (4x2), warp 32x48, k-chunk 32, fp32 accumulate.
// Kt = true K bound for IN_RELU bias (pad cols of A are zero & get no bias).
// ---------------------------------------------------------------------------
template <bool IN_RELU, bool OUT_RELU, bool OUT_SCALE>
__global__ void __launch_bounds__(256)
k_wgemm(const __half* __restrict__ A, int Kphys, int Kt, const float* __restrict__ binA,
        const __half* __restrict__ B,
        const float* __restrict__ bout, __half* __restrict__ C,
        const float* __restrict__ dinv, int M, int Nd, int Kp, int Np) {
    __shared__ __half Ash[2][128][40];
    __shared__ __half Bsh[2][32][104];
    __shared__ float stage[8][256];

    int tid = threadIdx.x;
    int wid = tid >> 5;
    int lane = tid & 31;
    int wm = wid & 3;
    int wn = wid >> 2;
    int row0 = blockIdx.x * 128;
    int col0 = blockIdx.y * 96;
    bool al8 = ((Nd & 3) == 0);

    wmma::fragment<wmma::accumulator, 16, 16, 16, float> acc[2][3];
#pragma unroll
    for (int mi = 0; mi < 2; mi++)
#pragma unroll
        for (int ni = 0; ni < 3; ni++) wmma::fill_fragment(acc[mi][ni], 0.0f);

    uint2 aReg[4], bReg[3];

    auto load_regs = [&](int ch) {
#pragma unroll
        for (int l = 0; l < 4; l++) {
            int i = tid + l * 256;
            int r = i >> 3, j4 = (i & 7) * 4;
            int grow = row0 + r, gk = ch * 32 + j4;
            uint2 u = make_uint2(0u, 0u);
            if (grow < M && gk < Kphys) {
                u = *(const uint2*)(A + (size_t)grow * Kphys + gk);
                if (IN_RELU && gk < Kt) {
                    const __half2* h = (const __half2*)&u;
                    float2 f0 = __half22float2(h[0]);
                    float2 f1 = __half22float2(h[1]);
                    float4 b = *(const float4*)(binA + gk);
                    __half2 o0 = __floats2half2_rn(fmaxf(f0.x + b.x, 0.f), fmaxf(f0.y + b.y, 0.f));
                    __half2 o1 = __floats2half2_rn(fmaxf(f1.x + b.z, 0.f), fmaxf(f1.y + b.w, 0.f));
                    u = make_uint2(*(uint32_t*)&o0, *(uint32_t*)&o1);
                } else if (IN_RELU) {
                    u = make_uint2(0u, 0u);   // pad cols: zero, no bias
                }
            }
            aReg[l] = u;
        }
#pragma unroll
        for (int l = 0; l < 3; l++) {
            int idx = tid + l * 256;
            int k = idx / 24, j4 = (idx - k * 24) * 4;
            size_t src = (size_t)(ch * 32 + k) * Np + col0 + j4;
            bReg[l] = *(const uint2*)(B + src);
        }
    };
    auto store_regs = [&](int buf) {
#pragma unroll
        for (int l = 0; l < 4; l++) {
            int i = tid + l * 256;
            int r = i >> 3, j4 = (i & 7) * 4;
            *(uint2*)&Ash[buf][r][j4] = aReg[l];
        }
#pragma unroll
        for (int l = 0; l < 3; l++) {
            int idx = tid + l * 256;
            int k = idx / 24, j4 = (idx - k * 24) * 4;
            *(uint2*)&Bsh[buf][k][j4] = bReg[l];
        }
    };

    int nch = Kp >> 5;
    load_regs(0);
    store_regs(0);
    __syncthreads();

    for (int ch = 0; ch < nch; ch++) {
        int buf = ch & 1;
        if (ch + 1 < nch) load_regs(ch + 1);
#pragma unroll
        for (int kk = 0; kk < 32; kk += 16) {
            wmma::fragment<wmma::matrix_a, 16, 16, 16, __half, wmma::row_major> af[2];
            wmma::fragment<wmma::matrix_b, 16, 16, 16, __half, wmma::row_major> bf[3];
#pragma unroll
            for (int mi = 0; mi < 2; mi++)
                wmma::load_matrix_sync(af[mi], &Ash[buf][wm * 32 + mi * 16][kk], 40);
#pragma unroll
            for (int ni = 0; ni < 3; ni++)
                wmma::load_matrix_sync(bf[ni], &Bsh[buf][kk][wn * 48 + ni * 16], 104);
#pragma unroll
            for (int mi = 0; mi < 2; mi++)
#pragma unroll
                for (int ni = 0; ni < 3; ni++)
                    wmma::mma_sync(acc[mi][ni], af[mi], bf[ni], acc[mi][ni]);
        }
        if (ch + 1 < nch) store_regs(buf ^ 1);
        __syncthreads();
    }

    // epilogue
#pragma unroll
    for (int mi = 0; mi < 2; mi++) {
#pragma unroll
        for (int ni = 0; ni < 3; ni++) {
            wmma::store_matrix_sync(stage[wid], acc[mi][ni], 16, wmma::mem_row_major);
            __syncwarp();
            int r = lane >> 1, cg = (lane & 1) * 8;
            int grow = row0 + wm * 32 + mi * 16 + r;
            int col = col0 + wn * 48 + ni * 16 + cg;
            if (grow < M) {
                float s = OUT_SCALE ? dinv[grow] : 1.0f;
                const float* st = &stage[wid][r * 16 + cg];
#pragma unroll
                for (int h4 = 0; h4 < 2; h4++) {
                    int cc = col + h4 * 4;
                    if (cc >= Nd) continue;
                    float f[4];
#pragma unroll
                    for (int j = 0; j < 4; j++) {
                        float v = st[h4 * 4 + j];
                        if (OUT_RELU) v = fmaxf(v + bout[cc + j], 0.0f);
                        if (OUT_SCALE) v *= s;
                        f[j] = v;
                    }
                    __half* dst = C + (size_t)grow * Nd + cc;
                    if (al8 && cc + 4 <= Nd) {
                        sth<4>(dst, f);
                    } else {
                        int nw = Nd - cc; if (nw > 4) nw = 4;
                        for (int j = 0; j + 2 <= nw; j += 2) sth<2>(dst + j, f + j);
                    }
                }
            }
            __syncwarp();
        }
    }
}

// ---------------------------------------------------------------------------
// Final fused head: p5 fp16 (stride 64) in, fp32 math, log_softmax out
// ---------------------------------------------------------------------------
__global__ void __launch_bounds__(128)
k_final(const __half* __restrict__ p5,
        const float* __restrict__ Wmu, const float* __restrict__ bmu,
        const float* __restrict__ Wls, const float* __restrict__ bls,
        const float* __restrict__ eps, float* __restrict__ out) {
    __shared__ float sWmu[42 * 21];
    __shared__ float sWls[42 * 21];
    __shared__ float sbmu[21];
    __shared__ float sbls[21];
    for (int i = threadIdx.x; i < 42 * 21; i += blockDim.x) {
        sWmu[i] = Wmu[i];
        sWls[i] = Wls[i];
    }
    if (threadIdx.x < 21) {
        sbmu[threadIdx.x] = bmu[threadIdx.x];
        sbls[threadIdx.x] = bls[threadIdx.x];
    }
    __syncthreads();

    int n = blockIdx.x * blockDim.x + threadIdx.x;
    if (n >= NN) return;

    float xr[42];
#pragma unroll
    for (int i = 0; i < 21; i++) {
        float2 t = __half22float2(*(const __half2*)(p5 + (size_t)n * 64 + 2 * i));
        xr[2 * i] = t.x; xr[2 * i + 1] = t.y;
    }

    float z[21];
#pragma unroll
    for (int j = 0; j < 21; j++) {
        float mu = sbmu[j];
        float ls = sbls[j];
#pragma unroll
        for (int i = 0; i < 42; i++) {
            mu += xr[i] * sWmu[i * 21 + j];
            ls += xr[i] * sWls[i * 21 + j];
        }
        ls = fminf(ls, 10.0f);
        z[j] = mu + eps[(size_t)n * 21 + j] * expf(ls);
    }
    float m = z[0];
#pragma unroll
    for (int j = 1; j < 21; j++) m = fmaxf(m, z[j]);
    float s = 0.0f;
#pragma unroll
    for (int j = 0; j < 21; j++) s += expf(z[j] - m);
    float lse = m + logf(s);
#pragma unroll
    for (int j = 0; j < 21; j++) out[(size_t)n * 21 + j] = z[j] - lse;
}

// ---------------------------------------------------------------------------
static inline int cdiv(long a, long b) { return (int)((a + b - 1) / b); }

extern "C" void kernel_launch(void* const* d_in, const int* in_sizes, int n_in,
                              void* d_out, int out_size) {
    const float* x    = (const float*)d_in[0];
    const int*   ei   = (const int*)  d_in[1];
    const float* eps  = (const float*)d_in[2];
    const float* W1   = (const float*)d_in[3];
    const float* b1   = (const float*)d_in[4];
    const float* W2   = (const float*)d_in[5];
    const float* b2   = (const float*)d_in[6];
    const float* W3   = (const float*)d_in[7];
    const float* b3   = (const float*)d_in[8];
    const float* W4   = (const float*)d_in[9];
    const float* b4   = (const float*)d_in[10];
    const float* Wmu  = (const float*)d_in[11];
    const float* bmu  = (const float*)d_in[12];
    const float* Wls  = (const float*)d_in[13];
    const float* bls  = (const float*)d_in[14];
    float* out = (float*)d_out;

    float* dinv;
    __half *xx, *p0, *a1, *tt2, *p2, *tt3, *p3, *tt4, *a4s, *p5;
    __half *w1, *w2, *w3, *w4;
    int *cnt, *off, *adj, *part;
    cudaGetSymbolAddress((void**)&dinv, g_dinv);
    cudaGetSymbolAddress((void**)&xx,  g_xx);
    cudaGetSymbolAddress((void**)&p0,  g_p0);
    cudaGetSymbolAddress((void**)&a1,  g_a1);
    cudaGetSymbolAddress((void**)&tt2, g_tt2);
    cudaGetSymbolAddress((void**)&p2,  g_p2);
    cudaGetSymbolAddress((void**)&tt3, g_tt3);
    cudaGetSymbolAddress((void**)&p3,  g_p3);
    cudaGetSymbolAddress((void**)&tt4, g_tt4);
    cudaGetSymbolAddress((void**)&a4s, g_a4s);
    cudaGetSymbolAddress((void**)&p5,  g_p5);
    cudaGetSymbolAddress((void**)&w1, g_w1);
    cudaGetSymbolAddress((void**)&w2, g_w2);
    cudaGetSymbolAddress((void**)&w3, g_w3);
    cudaGetSymbolAddress((void**)&w4, g_w4);
    cudaGetSymbolAddress((void**)&cnt, g_cnt);
    cudaGetSymbolAddress((void**)&off, g_off);
    cudaGetSymbolAddress((void**)&adj, g_adj);
    cudaGetSymbolAddress((void**)&part, g_part);

    const int* src = ei;
    const int* dst = ei + EE;

    // ---- fused prep + CSR build (+pad/scale fused into scan3) ----
    long prep_n = (long)NN > (long)WTOT ? (long)NN : (long)WTOT;
    k_prep<<<cdiv(prep_n, 256), 256>>>(W1, W2, W3, W4, w1, w2, w3, w4, cnt, off);
    k_count<<<cdiv(EE, 256), 256>>>(dst, cnt);
    k_scan1<<<NPART, 1024>>>(cnt, off, part, dinv);
    k_scan3<<<NPART, 1024>>>(off, part, x, dinv, xx);
    k_fill<<<cdiv(EE, 256), 256>>>(src, dst, off, cnt, adj);

    int gm = cdiv(NN, 128);

    // ---- conv1: aggregate xx (stride 64), wmma 35->336 (+b1, relu) ----
    k_agg<64, 8, false, 256, 64><<<cdiv(NN, 32), 256>>>(off, adj, dinv, xx, nullptr, p0);
    k_wgemm<false, true, false><<<dim3(gm, 4), 256>>>(
        p0, 64, 64, nullptr, w1, b1, a1, nullptr, NN, 336, 64, 384);

    // ---- conv2: wmma 336->168 (writes full 192-wide rows, zero pads), agg ----
    k_wgemm<false, false, true><<<dim3(gm, 2), 256>>>(
        a1, 336, 336, nullptr, w2, nullptr, tt2, dinv, NN, 192, 352, 192);
    k_agg<192, 8, false, 240, 192><<<cdiv(NN, 10), 240>>>(off, adj, dinv, tt2, nullptr, p2);

    // ---- conv3: in = relu(p2+b2) (Kt=168), wmma 168->84 (96-wide rows) ----
    k_wgemm<true, false, true><<<dim3(gm, 1), 256>>>(
        p2, 192, 168, b2, w3, nullptr, tt3, dinv, NN, 96, 192, 96);
    k_agg<96, 8, false, 252, 96><<<cdiv(NN, 21), 252>>>(off, adj, dinv, tt3, nullptr, p3);

    // ---- conv4: in = relu(p3+b3) (Kt=84), wmma 84->42 (64-wide rows) ----
    k_wgemm<true, false, true><<<dim3(gm, 1), 256>>>(
        p3, 96, 84, b3, w4, nullptr, tt4, dinv, NN, 64, 96, 96);
    k_agg<64, 8, true, 256, 42><<<cdiv(NN, 32), 256>>>(off, adj, dinv, tt4, b4, a4s);

    // ---- shared head propagation ----
    k_agg<64, 8, false, 256, 64><<<cdiv(NN, 32), 256>>>(off, adj, dinv, a4s, nullptr, p5);

    // ---- fused heads + reparam + log_softmax ----
    k_final<<<cdiv(NN, 128), 128>>>(p5, Wmu, bmu, Wls, bls, eps, out);
}

// round 16
// speedup vs baseline: 1.1184x; 1.1184x over previous
#include <cuda_runtime.h>
#include <cuda_fp16.h>
#include <mma.h>
#include <cstdint>

using namespace nvcuda;

#define NN 100000
#define EE 1600000
#define NPART 98   // ceil(NN/1024)

// ---------------------------------------------------------------------------
// Static device scratch — fp16 activations.
// tt4/a4s/p5 padded to 48 halves (96B = 3 exact 32B sectors per gathered row).
// ---------------------------------------------------------------------------
__device__ __align__(256) float  g_dinv[NN];
__device__ __align__(256) __half g_xx [NN * 36];
__device__ __align__(256) __half g_p0 [NN * 36];
__device__ __align__(256) __half g_a1 [NN * 336];
__device__ __align__(256) __half g_tt2[NN * 168];
__device__ __align__(256) __half g_p2 [NN * 168];
__device__ __align__(256) __half g_tt3[NN * 84];
__device__ __align__(256) __half g_p3 [NN * 84];
__device__ __align__(256) __half g_tt4[NN * 48];   // stride 48 (true 42)
__device__ __align__(256) __half g_a4s[NN * 48];
__device__ __align__(256) __half g_p5 [NN * 48];

// fp16 weight planes, zero-padded to [Kp][Np]
__device__ __align__(256) __half g_w1[64 * 384];
__device__ __align__(256) __half g_w2[352 * 192];
__device__ __align__(256) __half g_w3[192 * 96];
__device__ __align__(256) __half g_w4[96 * 96];

__device__ __align__(256) int g_cnt[NN];
__device__ __align__(256) int g_off[NN + 1];
__device__ __align__(256) int g_adj[EE];
__device__ __align__(256) int g_part[NPART];

// ---------------------------------------------------------------------------
// half vector load/store helpers
// ---------------------------------------------------------------------------
template <int V>
__device__ __forceinline__ void ldh(const __half* p, float* f) {
    if constexpr (V == 8) {
        uint4 u = *(const uint4*)p;
        const __half2* h = (const __half2*)&u;
#pragma unroll
        for (int k = 0; k < 4; k++) {
            float2 t = __half22float2(h[k]);
            f[2 * k] = t.x; f[2 * k + 1] = t.y;
        }
    } else if constexpr (V == 4) {
        uint2 u = *(const uint2*)p;
        const __half2* h = (const __half2*)&u;
#pragma unroll
        for (int k = 0; k < 2; k++) {
            float2 t = __half22float2(h[k]);
            f[2 * k] = t.x; f[2 * k + 1] = t.y;
        }
    } else {
        uint32_t u = *(const uint32_t*)p;
        float2 t = __half22float2(*(const __half2*)&u);
        f[0] = t.x; f[1] = t.y;
    }
}
template <int V>
__device__ __forceinline__ void sth(__half* p, const float* f) {
    if constexpr (V == 8) {
        uint4 u;
        __half2* h = (__half2*)&u;
#pragma unroll
        for (int k = 0; k < 4; k++)
            h[k] = __floats2half2_rn(f[2 * k], f[2 * k + 1]);
        *(uint4*)p = u;
    } else if constexpr (V == 4) {
        uint2 u;
        __half2* h = (__half2*)&u;
#pragma unroll
        for (int k = 0; k < 2; k++)
            h[k] = __floats2half2_rn(f[2 * k], f[2 * k + 1]);
        *(uint2*)p = u;
    } else {
        __half2 h = __floats2half2_rn(f[0], f[1]);
        *(uint32_t*)p = *(uint32_t*)&h;
    }
}

// ---------------------------------------------------------------------------
// Fused prep: zero cnt, off[NN]=EE, convert W1..W4 to fp16 padded planes.
// Launched with >= max(NN, WTOT) threads.
// ---------------------------------------------------------------------------
__device__ __forceinline__ void wcvt(const float* W, __half* o, int j,
                                     int K, int Nd, int Np) {
    int k = j / Np, n = j - k * Np;
    float v = (k < K && n < Nd) ? W[(size_t)k * Nd + n] : 0.0f;
    o[j] = __float2half_rn(v);
}
#define W1N (64 * 384)
#define W2N (352 * 192)
#define W3N (192 * 96)
#define W4N (96 * 96)
#define WTOT (W1N + W2N + W3N + W4N)
__global__ void k_prep(const float* __restrict__ W1, const float* __restrict__ W2,
                       const float* __restrict__ W3, const float* __restrict__ W4,
                       __half* __restrict__ w1, __half* __restrict__ w2,
                       __half* __restrict__ w3, __half* __restrict__ w4,
                       int* __restrict__ cnt, int* __restrict__ off) {
    int i = blockIdx.x * blockDim.x + threadIdx.x;
    if (i == 0) off[NN] = EE;
    if (i < NN) cnt[i] = 0;
    if (i < W1N) wcvt(W1, w1, i, 35, 336, 384);
    else if (i < W1N + W2N) wcvt(W2, w2, i - W1N, 336, 168, 192);
    else if (i < W1N + W2N + W3N) wcvt(W3, w3, i - W1N - W2N, 168, 84, 96);
    else if (i < WTOT) wcvt(W4, w4, i - W1N - W2N - W3N, 84, 42, 96);
}

// ---------------------------------------------------------------------------
// CSR build
// ---------------------------------------------------------------------------
__global__ void k_count(const int* __restrict__ dst, int* cnt) {
    int e = blockIdx.x * blockDim.x + threadIdx.x;
    if (e < EE) atomicAdd(&cnt[dst[e]], 1);
}
__global__ void k_scan1(const int* __restrict__ cnt, int* __restrict__ off,
                        int* __restrict__ part, float* __restrict__ dinv) {
    __shared__ int s[1024];
    int t = threadIdx.x;
    int i = blockIdx.x * 1024 + t;
    int v = (i < NN) ? cnt[i] : 0;
    if (i < NN) dinv[i] = rsqrtf((float)v + 1.0f);
    s[t] = v;
    __syncthreads();
    for (int d = 1; d < 1024; d <<= 1) {
        int u = (t >= d) ? s[t - d] : 0;
        __syncthreads();
        s[t] += u;
        __syncthreads();
    }
    if (i < NN) off[i] = s[t] - v;          // block-local exclusive
    if (t == 1023) part[blockIdx.x] = s[1023];
}
// scan3: finalize offsets + fused pad/scale x -> xx (stride 36)
__global__ void k_scan3(int* __restrict__ off, const int* __restrict__ part,
                        const float* __restrict__ x, const float* __restrict__ dinv,
                        __half* __restrict__ xx) {
    __shared__ int s[128];
    int t = threadIdx.x;
    if (t < 128) s[t] = (t < NPART) ? part[t] : 0;
    __syncthreads();
    for (int d = 1; d < 128; d <<= 1) {
        int u = 0;
        if (t < 128 && t >= d) u = s[t - d];
        __syncthreads();
        if (t < 128) s[t] += u;
        __syncthreads();
    }
    int base = (blockIdx.x > 0) ? s[blockIdx.x - 1] : 0;   // exclusive prefix
    int i = blockIdx.x * 1024 + t;
    if (i < NN) off[i] += base;
    // fused pad+scale: xx[n,c] = fp16(dinv[n] * pad(x)[n,c])
    for (long j = (long)blockIdx.x * 1024 + t; j < (long)NN * 36; j += (long)NPART * 1024) {
        int n = (int)(j / 36), c = (int)(j - (long)n * 36);
        float v = (c < 35) ? x[(size_t)n * 35 + c] : 0.0f;
        xx[j] = __float2half_rn(v * dinv[n]);
    }
}
// fill reusing cnt via atomic decrement
__global__ void k_fill(const int* __restrict__ src, const int* __restrict__ dst,
                       const int* __restrict__ off, int* cnt, int* __restrict__ adj) {
    int e = blockIdx.x * blockDim.x + threadIdx.x;
    if (e >= EE) return;
    int d = dst[e];
    int p = off[d] + atomicAdd(&cnt[d], -1) - 1;
    adj[p] = src[e];
}

// ---------------------------------------------------------------------------
// CSR gather aggregation (fp32 accumulate, 4-way unrolled)
// D = physical stride; DT = true width (RBS bias masked to c+v < DT).
// ---------------------------------------------------------------------------
template <int D, int V, bool RBS, int BLK, int DT>
__global__ void __launch_bounds__(BLK)
k_agg(const int* __restrict__ off, const int* __restrict__ adj,
      const float* __restrict__ dinv, const __half* __restrict__ tt,
      const float* __restrict__ bias, __half* __restrict__ p) {
    constexpr int G = D / V;
    constexpr int NPB = BLK / G;
    int g = threadIdx.x / G;
    int c = (threadIdx.x - g * G) * V;
    int node = blockIdx.x * NPB + g;
    if (g >= NPB || node >= NN) return;
    int ib = off[node], ie = off[node + 1];
    float acc[V], acc2[V];
    float t0[V], t1[V], t2[V], t3[V];
    ldh<V>(tt + (size_t)node * D + c, acc);
#pragma unroll
    for (int v = 0; v < V; v++) acc2[v] = 0.0f;
    int i = ib;
    for (; i + 4 <= ie; i += 4) {
        int s0 = adj[i], s1 = adj[i + 1], s2 = adj[i + 2], s3 = adj[i + 3];
        ldh<V>(tt + (size_t)s0 * D + c, t0);
        ldh<V>(tt + (size_t)s1 * D + c, t1);
        ldh<V>(tt + (size_t)s2 * D + c, t2);
        ldh<V>(tt + (size_t)s3 * D + c, t3);
#pragma unroll
        for (int v = 0; v < V; v++) {
            acc[v]  += t0[v] + t1[v];
            acc2[v] += t2[v] + t3[v];
        }
    }
    for (; i < ie; i++) {
        int s0 = adj[i];
        ldh<V>(tt + (size_t)s0 * D + c, t0);
#pragma unroll
        for (int v = 0; v < V; v++) acc[v] += t0[v];
    }
    float sc = dinv[node];
#pragma unroll
    for (int v = 0; v < V; v++) {
        float f = (acc[v] + acc2[v]) * sc;
        if (RBS) f = ((c + v) < DT) ? fmaxf(f + bias[c + v], 0.0f) * sc : 0.0f;
        acc[v] = f;
    }
    sth<V>(p + (size_t)node * D + c, acc);
}

// ---------------------------------------------------------------------------
// wmma fp16 GEMM, register-staged double-buffered chunks (R14-proven).
// Block 128x96, 8 warps (4x2), warp 32x48, k-chunk 32, fp32 accumulate.
// ---------------------------------------------------------------------------
template <bool IN_RELU, bool OUT_RELU, bool OUT_SCALE>
__global__ void __launch_bounds__(256)
k_wgemm(const __half* __restrict__ A, int Kphys, const float* __restrict__ binA,
        const __half* __restrict__ B,
        const float* __restrict__ bout, __half* __restrict__ C,
        const float* __restrict__ dinv, int M, int Nd, int Kp, int Np) {
    __shared__ __half Ash[2][128][40];
    __shared__ __half Bsh[2][32][104];
    __shared__ float stage[8][256];

    int tid = threadIdx.x;
    int wid = tid >> 5;
    int lane = tid & 31;
    int wm = wid & 3;
    int wn = wid >> 2;
    int row0 = blockIdx.x * 128;
    int col0 = blockIdx.y * 96;
    bool al8 = ((Nd & 3) == 0);

    wmma::fragment<wmma::accumulator, 16, 16, 16, float> acc[2][3];
#pragma unroll
    for (int mi = 0; mi < 2; mi++)
#pragma unroll
        for (int ni = 0; ni < 3; ni++) wmma::fill_fragment(acc[mi][ni], 0.0f);

    uint2 aReg[4], bReg[3];

    auto load_regs = [&](int ch) {
#pragma unroll
        for (int l = 0; l < 4; l++) {
            int i = tid + l * 256;
            int r = i >> 3, j4 = (i & 7) * 4;
            int grow = row0 + r, gk = ch * 32 + j4;
            uint2 u = make_uint2(0u, 0u);
            if (grow < M && gk < Kphys) {
                u = *(const uint2*)(A + (size_t)grow * Kphys + gk);
                if (IN_RELU) {
                    const __half2* h = (const __half2*)&u;
                    float2 f0 = __half22float2(h[0]);
                    float2 f1 = __half22float2(h[1]);
                    float4 b = *(const float4*)(binA + gk);
                    __half2 o0 = __floats2half2_rn(fmaxf(f0.x + b.x, 0.f), fmaxf(f0.y + b.y, 0.f));
                    __half2 o1 = __floats2half2_rn(fmaxf(f1.x + b.z, 0.f), fmaxf(f1.y + b.w, 0.f));
                    u = make_uint2(*(uint32_t*)&o0, *(uint32_t*)&o1);
                }
            }
            aReg[l] = u;
        }
#pragma unroll
        for (int l = 0; l < 3; l++) {
            int idx = tid + l * 256;
            int k = idx / 24, j4 = (idx - k * 24) * 4;
            size_t src = (size_t)(ch * 32 + k) * Np + col0 + j4;
            bReg[l] = *(const uint2*)(B + src);
        }
    };
    auto store_regs = [&](int buf) {
#pragma unroll
        for (int l = 0; l < 4; l++) {
            int i = tid + l * 256;
            int r = i >> 3, j4 = (i & 7) * 4;
            *(uint2*)&Ash[buf][r][j4] = aReg[l];
        }
#pragma unroll
        for (int l = 0; l < 3; l++) {
            int idx = tid + l * 256;
            int k = idx / 24, j4 = (idx - k * 24) * 4;
            *(uint2*)&Bsh[buf][k][j4] = bReg[l];
        }
    };

    int nch = Kp >> 5;
    load_regs(0);
    store_regs(0);
    __syncthreads();

    for (int ch = 0; ch < nch; ch++) {
        int buf = ch & 1;
        if (ch + 1 < nch) load_regs(ch + 1);
#pragma unroll
        for (int kk = 0; kk < 32; kk += 16) {
            wmma::fragment<wmma::matrix_a, 16, 16, 16, __half, wmma::row_major> af[2];
            wmma::fragment<wmma::matrix_b, 16, 16, 16, __half, wmma::row_major> bf[3];
#pragma unroll
            for (int mi = 0; mi < 2; mi++)
                wmma::load_matrix_sync(af[mi], &Ash[buf][wm * 32 + mi * 16][kk], 40);
#pragma unroll
            for (int ni = 0; ni < 3; ni++)
                wmma::load_matrix_sync(bf[ni], &Bsh[buf][kk][wn * 48 + ni * 16], 104);
#pragma unroll
            for (int mi = 0; mi < 2; mi++)
#pragma unroll
                for (int ni = 0; ni < 3; ni++)
                    wmma::mma_sync(acc[mi][ni], af[mi], bf[ni], acc[mi][ni]);
        }
        if (ch + 1 < nch) store_regs(buf ^ 1);
        __syncthreads();
    }

    // epilogue
#pragma unroll
    for (int mi = 0; mi < 2; mi++) {
#pragma unroll
        for (int ni = 0; ni < 3; ni++) {
            wmma::store_matrix_sync(stage[wid], acc[mi][ni], 16, wmma::mem_row_major);
            __syncwarp();
            int r = lane >> 1, cg = (lane & 1) * 8;
            int grow = row0 + wm * 32 + mi * 16 + r;
            int col = col0 + wn * 48 + ni * 16 + cg;
            if (grow < M) {
                float s = OUT_SCALE ? dinv[grow] : 1.0f;
                const float* st = &stage[wid][r * 16 + cg];
#pragma unroll
                for (int h4 = 0; h4 < 2; h4++) {
                    int cc = col + h4 * 4;
                    if (cc >= Nd) continue;
                    float f[4];
#pragma unroll
                    for (int j = 0; j < 4; j++) {
                        float v = st[h4 * 4 + j];
                        if (OUT_RELU) v = fmaxf(v + bout[cc + j], 0.0f);
                        if (OUT_SCALE) v *= s;
                        f[j] = v;
                    }
                    __half* dst = C + (size_t)grow * Nd + cc;
                    if (al8 && cc + 4 <= Nd) {
                        sth<4>(dst, f);
                    } else {
                        int nw = Nd - cc; if (nw > 4) nw = 4;
                        for (int j = 0; j + 2 <= nw; j += 2) sth<2>(dst + j, f + j);
                    }
                }
            }
            __syncwarp();
        }
    }
}

// ---------------------------------------------------------------------------
// Final fused head: p5 fp16 (stride 48) in, fp32 math, log_softmax out
// ---------------------------------------------------------------------------
__global__ void __launch_bounds__(128)
k_final(const __half* __restrict__ p5,
        const float* __restrict__ Wmu, const float* __restrict__ bmu,
        const float* __restrict__ Wls, const float* __restrict__ bls,
        const float* __restrict__ eps, float* __restrict__ out) {
    __shared__ float sWmu[42 * 21];
    __shared__ float sWls[42 * 21];
    __shared__ float sbmu[21];
    __shared__ float sbls[21];
    for (int i = threadIdx.x; i < 42 * 21; i += blockDim.x) {
        sWmu[i] = Wmu[i];
        sWls[i] = Wls[i];
    }
    if (threadIdx.x < 21) {
        sbmu[threadIdx.x] = bmu[threadIdx.x];
        sbls[threadIdx.x] = bls[threadIdx.x];
    }
    __syncthreads();

    int n = blockIdx.x * blockDim.x + threadIdx.x;
    if (n >= NN) return;

    float xr[42];
#pragma unroll
    for (int i = 0; i < 21; i++) {
        float2 t = __half22float2(*(const __half2*)(p5 + (size_t)n * 48 + 2 * i));
        xr[2 * i] = t.x; xr[2 * i + 1] = t.y;
    }

    float z[21];
#pragma unroll
    for (int j = 0; j < 21; j++) {
        float mu = sbmu[j];
        float ls = sbls[j];
#pragma unroll
        for (int i = 0; i < 42; i++) {
            mu += xr[i] * sWmu[i * 21 + j];
            ls += xr[i] * sWls[i * 21 + j];
        }
        ls = fminf(ls, 10.0f);
        z[j] = mu + eps[(size_t)n * 21 + j] * expf(ls);
    }
    float m = z[0];
#pragma unroll
    for (int j = 1; j < 21; j++) m = fmaxf(m, z[j]);
    float s = 0.0f;
#pragma unroll
    for (int j = 0; j < 21; j++) s += expf(z[j] - m);
    float lse = m + logf(s);
#pragma unroll
    for (int j = 0; j < 21; j++) out[(size_t)n * 21 + j] = z[j] - lse;
}

// ---------------------------------------------------------------------------
static inline int cdiv(long a, long b) { return (int)((a + b - 1) / b); }

extern "C" void kernel_launch(void* const* d_in, const int* in_sizes, int n_in,
                              void* d_out, int out_size) {
    const float* x    = (const float*)d_in[0];
    const int*   ei   = (const int*)  d_in[1];
    const float* eps  = (const float*)d_in[2];
    const float* W1   = (const float*)d_in[3];
    const float* b1   = (const float*)d_in[4];
    const float* W2   = (const float*)d_in[5];
    const float* b2   = (const float*)d_in[6];
    const float* W3   = (const float*)d_in[7];
    const float* b3   = (const float*)d_in[8];
    const float* W4   = (const float*)d_in[9];
    const float* b4   = (const float*)d_in[10];
    const float* Wmu  = (const float*)d_in[11];
    const float* bmu  = (const float*)d_in[12];
    const float* Wls  = (const float*)d_in[13];
    const float* bls  = (const float*)d_in[14];
    float* out = (float*)d_out;

    float* dinv;
    __half *xx, *p0, *a1, *tt2, *p2, *tt3, *p3, *tt4, *a4s, *p5;
    __half *w1, *w2, *w3, *w4;
    int *cnt, *off, *adj, *part;
    cudaGetSymbolAddress((void**)&dinv, g_dinv);
    cudaGetSymbolAddress((void**)&xx,  g_xx);
    cudaGetSymbolAddress((void**)&p0,  g_p0);
    cudaGetSymbolAddress((void**)&a1,  g_a1);
    cudaGetSymbolAddress((void**)&tt2, g_tt2);
    cudaGetSymbolAddress((void**)&p2,  g_p2);
    cudaGetSymbolAddress((void**)&tt3, g_tt3);
    cudaGetSymbolAddress((void**)&p3,  g_p3);
    cudaGetSymbolAddress((void**)&tt4, g_tt4);
    cudaGetSymbolAddress((void**)&a4s, g_a4s);
    cudaGetSymbolAddress((void**)&p5,  g_p5);
    cudaGetSymbolAddress((void**)&w1, g_w1);
    cudaGetSymbolAddress((void**)&w2, g_w2);
    cudaGetSymbolAddress((void**)&w3, g_w3);
    cudaGetSymbolAddress((void**)&w4, g_w4);
    cudaGetSymbolAddress((void**)&cnt, g_cnt);
    cudaGetSymbolAddress((void**)&off, g_off);
    cudaGetSymbolAddress((void**)&adj, g_adj);
    cudaGetSymbolAddress((void**)&part, g_part);

    const int* src = ei;
    const int* dst = ei + EE;

    // ---- fused prep + CSR build (+pad/scale fused into scan3) ----
    long prep_n = (long)NN > (long)WTOT ? (long)NN : (long)WTOT;
    k_prep<<<cdiv(prep_n, 256), 256>>>(W1, W2, W3, W4, w1, w2, w3, w4, cnt, off);
    k_count<<<cdiv(EE, 256), 256>>>(dst, cnt);
    k_scan1<<<NPART, 1024>>>(cnt, off, part, dinv);
    k_scan3<<<NPART, 1024>>>(off, part, x, dinv, xx);
    k_fill<<<cdiv(EE, 256), 256>>>(src, dst, off, cnt, adj);

    int gm = cdiv(NN, 128);

    // ---- conv1: aggregate xx (D=36), wmma 35->336 (+b1, relu) ----
    k_agg<36, 4, false, 252, 36><<<cdiv(NN, 28), 252>>>(off, adj, dinv, xx, nullptr, p0);
    k_wgemm<false, true, false><<<dim3(gm, 4), 256>>>(
        p0, 36, nullptr, w1, b1, a1, nullptr, NN, 336, 64, 384);

    // ---- conv2: wmma 336->168 (scaled out), aggregate ----
    k_wgemm<false, false, true><<<dim3(gm, 2), 256>>>(
        a1, 336, nullptr, w2, nullptr, tt2, dinv, NN, 168, 352, 192);
    k_agg<168, 8, false, 252, 168><<<cdiv(NN, 12), 252>>>(off, adj, dinv, tt2, nullptr, p2);

    // ---- conv3: in = relu(p2+b2), wmma 168->84, scaled out ----
    k_wgemm<true, false, true><<<dim3(gm, 1), 256>>>(
        p2, 168, b2, w3, nullptr, tt3, dinv, NN, 84, 192, 96);
    k_agg<84, 4, false, 252, 84><<<cdiv(NN, 12), 252>>>(off, adj, dinv, tt3, nullptr, p3);

    // ---- conv4: in = relu(p3+b3), wmma 84->42 into 48-wide rows ----
    k_wgemm<true, false, true><<<dim3(gm, 1), 256>>>(
        p3, 84, b3, w4, nullptr, tt4, dinv, NN, 48, 96, 96);
    k_agg<48, 4, true, 252, 42><<<cdiv(NN, 21), 252>>>(off, adj, dinv, tt4, b4, a4s);

    // ---- shared head propagation (48-wide) ----
    k_agg<48, 4, false, 252, 48><<<cdiv(NN, 21), 252>>>(off, adj, dinv, a4s, nullptr, p5);

    // ---- fused heads + reparam + log_softmax ----
    k_final<<<cdiv(NN, 128), 128>>>(p5, Wmu, bmu, Wls, bls, eps, out);
}